// round 1
// baseline (speedup 1.0000x reference)
#include <cuda_runtime.h>
#include <math.h>

// Problem constants
#define NB    16      // batch
#define NPTS  4096    // N (query points)
#define MPTS  1024    // M (source points)
#define CH2   256     // points2 channels
#define CH1   128     // points1 channels
#define OUT1  256     // MLP layer 1 out
#define OUT2  256     // MLP layer 2 out
#define LDA_W1 384    // W1 is (256, 384): [interp(256) | points1(128)]

// ---- scratch (static device memory; no allocations allowed) ----
__device__ int   g_idx[NB * NPTS * 3];                    // 3-NN indices
__device__ float g_wgt[NB * NPTS * 3];                    // 3-NN weights
__device__ float g_T  [NB * OUT1 * MPTS];                 // T = W1[:, :256] @ points2  (16 MB)
__device__ float g_y1 [NB * OUT1 * NPTS];                 // layer-1 activations        (64 MB)

// ===========================================================================
// Kernel 1: three_nn + weights.
// One thread per query point n; xyz2[b] staged in smem.
// d2 computed as sq1 + sq2 - 2*inner to match the reference formula.
// ===========================================================================
__global__ __launch_bounds__(256)
void three_nn_kernel(const float* __restrict__ xyz1, const float* __restrict__ xyz2)
{
    __shared__ float sx[MPTS], sy[MPTS], sz[MPTS], ss[MPTS];
    const int b = blockIdx.y;
    const float* x2 = xyz2 + (size_t)b * 3 * MPTS;
    for (int i = threadIdx.x; i < MPTS; i += blockDim.x) {
        float xv = x2[i], yv = x2[MPTS + i], zv = x2[2 * MPTS + i];
        sx[i] = xv; sy[i] = yv; sz[i] = zv;
        ss[i] = xv * xv + yv * yv + zv * zv;
    }
    __syncthreads();

    const int n = blockIdx.x * blockDim.x + threadIdx.x;
    const float* x1 = xyz1 + (size_t)b * 3 * NPTS;
    const float px = x1[n], py = x1[NPTS + n], pz = x1[2 * NPTS + n];
    const float sq1 = px * px + py * py + pz * pz;

    float d0 = 1e30f, d1 = 1e30f, d2 = 1e30f;
    int   i0 = 0, i1 = 0, i2 = 0;

    #pragma unroll 4
    for (int m = 0; m < MPTS; m++) {
        float inner = fmaf(px, sx[m], fmaf(py, sy[m], pz * sz[m]));
        float d = fmaf(-2.0f, inner, sq1 + ss[m]);
        if (d < d2) {
            if (d < d1) {
                d2 = d1; i2 = i1;
                if (d < d0) { d1 = d0; i1 = i0; d0 = d; i0 = m; }
                else        { d1 = d;  i1 = m; }
            } else { d2 = d; i2 = m; }
        }
    }

    // dist = max(sqrt(max(d2, 1e-20)), 1e-10); w = (1/dist) / sum
    float r0 = 1.0f / fmaxf(sqrtf(fmaxf(d0, 1e-20f)), 1e-10f);
    float r1 = 1.0f / fmaxf(sqrtf(fmaxf(d1, 1e-20f)), 1e-10f);
    float r2 = 1.0f / fmaxf(sqrtf(fmaxf(d2, 1e-20f)), 1e-10f);
    float inv = 1.0f / (r0 + r1 + r2);

    const int base = (b * NPTS + n) * 3;
    g_idx[base + 0] = i0; g_idx[base + 1] = i1; g_idx[base + 2] = i2;
    g_wgt[base + 0] = r0 * inv; g_wgt[base + 1] = r1 * inv; g_wgt[base + 2] = r2 * inv;
}

// ===========================================================================
// Generic SGEMM: C[b] = act(A[:, colOff:colOff+K] @ X[b] + bias (+ gather))
// 128x128 block tile, 256 threads, 8x8 microtile (split-column mapping for
// conflict-free LDS.128), BK=16.
//
// MODE 0: T   = W1[:, :256]   @ points2   (K=256, N=1024)            -> g_T
// MODE 1: y1  = relu(W1[:,256:]@ points1 + b1 + Sum_j w_j T[:,idx_j]) -> g_y1
// MODE 2: out = relu(W2        @ y1      + b2)                       -> d_out
// ===========================================================================
template <int MODE>
__global__ __launch_bounds__(256)
void gemm_kernel(const float* __restrict__ A,
                 const float* __restrict__ Xext,
                 float*       __restrict__ Cext,
                 const float* __restrict__ bias)
{
    constexpr int K    = (MODE == 1) ? 128 : 256;
    constexpr int LDA  = (MODE == 2) ? 256 : LDA_W1;
    constexpr int COFF = (MODE == 1) ? 256 : 0;
    constexpr int LDX  = (MODE == 0) ? MPTS : NPTS;
    constexpr int XBS  = (MODE == 0) ? CH2 * MPTS : (MODE == 1) ? CH1 * NPTS : OUT1 * NPTS;
    constexpr int LDC  = (MODE == 0) ? MPTS : NPTS;
    constexpr int CBS  = (MODE == 0) ? OUT1 * MPTS : OUT1 * NPTS;

    __shared__ float As[16][128];
    __shared__ float Bs[16][128];

    const int b     = blockIdx.z;
    const int nBase = blockIdx.x * 128;
    const int oBase = blockIdx.y * 128;
    const int tid   = threadIdx.x;
    const int ty    = tid >> 4;    // 0..15
    const int tx    = tid & 15;    // 0..15

    const float* Xb = (MODE == 2) ? (g_y1 + (size_t)b * XBS) : (Xext + (size_t)b * XBS);
    float*       Cb = (MODE == 0) ? (g_T  + (size_t)b * CBS)
                   : (MODE == 1) ? (g_y1 + (size_t)b * CBS)
                                 : (Cext + (size_t)b * CBS);

    float acc[8][8];
    #pragma unroll
    for (int i = 0; i < 8; i++)
        #pragma unroll
        for (int j = 0; j < 8; j++) acc[i][j] = 0.0f;

    for (int k0 = 0; k0 < K; k0 += 16) {
        // Load A tile (128 rows x 16 k), store transposed As[k][row]
        #pragma unroll
        for (int l = 0; l < 2; l++) {
            int lin = tid + l * 256;
            int row = lin >> 2;
            int c4  = (lin & 3) * 4;
            float4 v = *reinterpret_cast<const float4*>(
                &A[(size_t)(oBase + row) * LDA + COFF + k0 + c4]);
            As[c4 + 0][row] = v.x; As[c4 + 1][row] = v.y;
            As[c4 + 2][row] = v.z; As[c4 + 3][row] = v.w;
        }
        // Load X tile (16 k x 128 n)
        #pragma unroll
        for (int l = 0; l < 2; l++) {
            int lin = tid + l * 256;
            int kr  = lin >> 5;
            int c4  = (lin & 31) * 4;
            *reinterpret_cast<float4*>(&Bs[kr][c4]) =
                *reinterpret_cast<const float4*>(&Xb[(size_t)(k0 + kr) * LDX + nBase + c4]);
        }
        __syncthreads();

        #pragma unroll
        for (int kk = 0; kk < 16; kk++) {
            float4 a0 = *reinterpret_cast<const float4*>(&As[kk][ty * 4]);
            float4 a1 = *reinterpret_cast<const float4*>(&As[kk][64 + ty * 4]);
            float4 b0 = *reinterpret_cast<const float4*>(&Bs[kk][tx * 4]);
            float4 b1 = *reinterpret_cast<const float4*>(&Bs[kk][64 + tx * 4]);
            float av[8] = {a0.x, a0.y, a0.z, a0.w, a1.x, a1.y, a1.z, a1.w};
            float bv[8] = {b0.x, b0.y, b0.z, b0.w, b1.x, b1.y, b1.z, b1.w};
            #pragma unroll
            for (int i = 0; i < 8; i++)
                #pragma unroll
                for (int j = 0; j < 8; j++)
                    acc[i][j] = fmaf(av[i], bv[j], acc[i][j]);
        }
        __syncthreads();
    }

    // ---- epilogue ----
    // row o of microtile element i, col n of element j (split-column mapping)
    // rowOf(i) = (i<4) ? ty*4+i : 64+ty*4+(i-4); colOf(j) likewise with tx.

    if (MODE == 1) {
        // gather: acc[i][j] += Sum_k w_k * T[b][o][idx_k]
        const float* Tb = g_T   + (size_t)b * OUT1 * MPTS;
        const int*   ib = g_idx + (size_t)b * NPTS * 3;
        const float* wb = g_wgt + (size_t)b * NPTS * 3;
        #pragma unroll
        for (int j = 0; j < 8; j++) {
            int n  = nBase + ((j < 4) ? tx * 4 + j : 64 + tx * 4 + (j - 4));
            int j0 = ib[n * 3 + 0], j1 = ib[n * 3 + 1], j2 = ib[n * 3 + 2];
            float w0 = wb[n * 3 + 0], w1 = wb[n * 3 + 1], w2 = wb[n * 3 + 2];
            #pragma unroll
            for (int i = 0; i < 8; i++) {
                int o = oBase + ((i < 4) ? ty * 4 + i : 64 + ty * 4 + (i - 4));
                const float* tr = Tb + (size_t)o * MPTS;
                acc[i][j] += w0 * tr[j0] + w1 * tr[j1] + w2 * tr[j2];
            }
        }
    }

    #pragma unroll
    for (int i = 0; i < 8; i++) {
        int o = oBase + ((i < 4) ? ty * 4 + i : 64 + ty * 4 + (i - 4));
        float bv = (MODE == 0) ? 0.0f : bias[o];
        #pragma unroll
        for (int j = 0; j < 8; j++) {
            float v = acc[i][j] + bv;
            if (MODE != 0) v = fmaxf(v, 0.0f);
            acc[i][j] = v;
        }
        float4 v0 = make_float4(acc[i][0], acc[i][1], acc[i][2], acc[i][3]);
        float4 v1 = make_float4(acc[i][4], acc[i][5], acc[i][6], acc[i][7]);
        *reinterpret_cast<float4*>(&Cb[(size_t)o * LDC + nBase + tx * 4])      = v0;
        *reinterpret_cast<float4*>(&Cb[(size_t)o * LDC + nBase + 64 + tx * 4]) = v1;
    }
}

// ===========================================================================
extern "C" void kernel_launch(void* const* d_in, const int* in_sizes, int n_in,
                              void* d_out, int out_size)
{
    const float* xyz1    = (const float*)d_in[0];  // (16, 3, 4096)
    const float* xyz2    = (const float*)d_in[1];  // (16, 3, 1024)
    const float* points1 = (const float*)d_in[2];  // (16, 128, 4096)
    const float* points2 = (const float*)d_in[3];  // (16, 256, 1024)
    const float* W1      = (const float*)d_in[4];  // (256, 384)
    const float* b1      = (const float*)d_in[5];  // (256)
    const float* W2      = (const float*)d_in[6];  // (256, 256)
    const float* b2      = (const float*)d_in[7];  // (256)
    float*       out     = (float*)d_out;          // (16, 256, 4096)

    // 1) 3-NN search + interpolation weights
    three_nn_kernel<<<dim3(NPTS / 256, NB), 256>>>(xyz1, xyz2);

    // 2) T = W1[:, :256] @ points2     (per batch, 256x1024)
    gemm_kernel<0><<<dim3(MPTS / 128, OUT1 / 128, NB), 256>>>(W1, points2, nullptr, nullptr);

    // 3) y1 = relu(W1[:, 256:] @ points1 + b1 + gathered-weighted T)
    gemm_kernel<1><<<dim3(NPTS / 128, OUT1 / 128, NB), 256>>>(W1, points1, nullptr, b1);

    // 4) out = relu(W2 @ y1 + b2)
    gemm_kernel<2><<<dim3(NPTS / 128, OUT2 / 128, NB), 256>>>(W2, nullptr, out, b2);
}

// round 3
// speedup vs baseline: 1.3515x; 1.3515x over previous
#include <cuda_runtime.h>
#include <math.h>
#include <cstdint>

// Problem constants
#define NB    16
#define NPTS  4096
#define MPTS  1024
#define CH2   256
#define CH1   128
#define OUT1  256
#define OUT2  256
#define LDA_W1 384

// ---- scratch ----
__device__ int   g_idx[NB * NPTS * 3];
__device__ float g_wgt[NB * NPTS * 3];
__device__ float g_T  [NB * OUT1 * MPTS];   // T = W1[:, :256] @ points2
__device__ float g_y1 [NB * OUT1 * NPTS];   // layer-1 activations [b][k][n]

// ===========================================================================
// Kernel 1: three_nn + weights
// ===========================================================================
__global__ __launch_bounds__(256)
void three_nn_kernel(const float* __restrict__ xyz1, const float* __restrict__ xyz2)
{
    __shared__ float sx[MPTS], sy[MPTS], sz[MPTS], ss[MPTS];
    const int b = blockIdx.y;
    const float* x2 = xyz2 + (size_t)b * 3 * MPTS;
    for (int i = threadIdx.x; i < MPTS; i += blockDim.x) {
        float xv = x2[i], yv = x2[MPTS + i], zv = x2[2 * MPTS + i];
        sx[i] = xv; sy[i] = yv; sz[i] = zv;
        ss[i] = xv * xv + yv * yv + zv * zv;
    }
    __syncthreads();

    const int n = blockIdx.x * blockDim.x + threadIdx.x;
    const float* x1 = xyz1 + (size_t)b * 3 * NPTS;
    const float px = x1[n], py = x1[NPTS + n], pz = x1[2 * NPTS + n];
    const float sq1 = px * px + py * py + pz * pz;

    float d0 = 1e30f, d1 = 1e30f, d2 = 1e30f;
    int   i0 = 0, i1 = 0, i2 = 0;

    #pragma unroll 4
    for (int m = 0; m < MPTS; m++) {
        float inner = fmaf(px, sx[m], fmaf(py, sy[m], pz * sz[m]));
        float d = fmaf(-2.0f, inner, sq1 + ss[m]);
        if (d < d2) {
            if (d < d1) {
                d2 = d1; i2 = i1;
                if (d < d0) { d1 = d0; i1 = i0; d0 = d; i0 = m; }
                else        { d1 = d;  i1 = m; }
            } else { d2 = d; i2 = m; }
        }
    }

    float r0 = 1.0f / fmaxf(sqrtf(fmaxf(d0, 1e-20f)), 1e-10f);
    float r1 = 1.0f / fmaxf(sqrtf(fmaxf(d1, 1e-20f)), 1e-10f);
    float r2 = 1.0f / fmaxf(sqrtf(fmaxf(d2, 1e-20f)), 1e-10f);
    float inv = 1.0f / (r0 + r1 + r2);

    const int base = (b * NPTS + n) * 3;
    g_idx[base + 0] = i0; g_idx[base + 1] = i1; g_idx[base + 2] = i2;
    g_wgt[base + 0] = r0 * inv; g_wgt[base + 1] = r1 * inv; g_wgt[base + 2] = r2 * inv;
}

// ===========================================================================
// tf32 mma.sync GEMM (HMMA path; tcgen05 not available on this PTX target).
//   MODE 0: T   = W1[:, :256] @ points2                     -> g_T
//   MODE 1: y1  = relu(W1[:,256:] @ points1 + b1 + gather)  -> g_y1
//   MODE 2: out = relu(W2 @ y1 + b2)                        -> d_out
// CTA tile 128x128, BK=32, 8 warps (2 rows x 4 cols), warp tile 64x32,
// mma.m16n8k8.tf32.
// ===========================================================================
__device__ __forceinline__ uint32_t f2tf32(float x) {
    uint32_t r;
    asm("cvt.rna.tf32.f32 %0, %1;" : "=r"(r) : "f"(x));
    return r;
}

#define APAD 4   // As stride 36 words: frag bank = 4*r + c  (bijective)
#define BPAD 8   // Bs stride 136 words: frag bank = 8*c + n (bijective)

template <int MODE>
__global__ __launch_bounds__(256)
void gemm_mma(const float* __restrict__ A,
              const float* __restrict__ X,
              const float* __restrict__ bias,
              float*       __restrict__ Cext)
{
    constexpr int K    = (MODE == 1) ? 128 : 256;
    constexpr int LDA  = (MODE == 2) ? 256 : LDA_W1;
    constexpr int COFF = (MODE == 1) ? 256 : 0;
    constexpr int LDX  = (MODE == 0) ? MPTS : NPTS;
    constexpr int XBS  = (MODE == 0) ? CH2 * MPTS : (MODE == 1) ? CH1 * NPTS : OUT1 * NPTS;
    constexpr int LDC  = (MODE == 0) ? MPTS : NPTS;
    constexpr int CBS  = (MODE == 0) ? OUT1 * MPTS : OUT1 * NPTS;

    __shared__ uint32_t As[128][32 + APAD];   // [o][k]   18.4 KB
    __shared__ uint32_t Bs[32][128 + BPAD];   // [k][n]   17.4 KB

    const int b     = blockIdx.z;
    const int nBase = blockIdx.x * 128;
    const int oBase = blockIdx.y * 128;
    const int tid   = threadIdx.x;
    const int wid   = tid >> 5;
    const int lane  = tid & 31;
    const int g     = lane >> 2;   // 0..7
    const int tc    = lane & 3;    // 0..3

    const int oW = (wid >> 2) * 64;   // warp row base within tile
    const int nW = (wid & 3) * 32;    // warp col base within tile

    const float* Xb = (MODE == 2) ? (g_y1 + (size_t)b * XBS) : (X + (size_t)b * XBS);
    float*       Cb = (MODE == 0) ? (g_T  + (size_t)b * CBS)
                   : (MODE == 1) ? (g_y1 + (size_t)b * CBS)
                                 : (Cext + (size_t)b * CBS);

    float c[4][4][4];   // [mi][ni][reg]
    #pragma unroll
    for (int mi = 0; mi < 4; mi++)
        #pragma unroll
        for (int ni = 0; ni < 4; ni++)
            #pragma unroll
            for (int q = 0; q < 4; q++) c[mi][ni][q] = 0.0f;

    for (int k0 = 0; k0 < K; k0 += 32) {
        // --- load A tile (128 o x 32 k), cvt to tf32, natural [o][k] layout ---
        #pragma unroll
        for (int l = 0; l < 4; l++) {
            int lin = tid + l * 256;
            int row = lin >> 3;
            int c4  = (lin & 7) * 4;
            float4 v = *reinterpret_cast<const float4*>(
                &A[(size_t)(oBase + row) * LDA + COFF + k0 + c4]);
            uint4 t = make_uint4(f2tf32(v.x), f2tf32(v.y), f2tf32(v.z), f2tf32(v.w));
            *reinterpret_cast<uint4*>(&As[row][c4]) = t;
        }
        // --- load B tile (32 k x 128 n) ---
        #pragma unroll
        for (int l = 0; l < 4; l++) {
            int lin = tid + l * 256;
            int kr  = lin >> 5;
            int c4  = (lin & 31) * 4;
            float4 v = *reinterpret_cast<const float4*>(
                &Xb[(size_t)(k0 + kr) * LDX + nBase + c4]);
            uint4 t = make_uint4(f2tf32(v.x), f2tf32(v.y), f2tf32(v.z), f2tf32(v.w));
            *reinterpret_cast<uint4*>(&Bs[kr][c4]) = t;
        }
        __syncthreads();

        #pragma unroll
        for (int kk = 0; kk < 32; kk += 8) {
            // A fragments: a0=(r,c) a1=(r+8,c) a2=(r,c+4) a3=(r+8,c+4)
            uint32_t a[4][4];
            #pragma unroll
            for (int mi = 0; mi < 4; mi++) {
                int rb = oW + mi * 16;
                a[mi][0] = As[rb + g    ][kk + tc    ];
                a[mi][1] = As[rb + g + 8][kk + tc    ];
                a[mi][2] = As[rb + g    ][kk + tc + 4];
                a[mi][3] = As[rb + g + 8][kk + tc + 4];
            }
            // B fragments: b0=(k=tc, n=g)  b1=(k=tc+4, n=g)
            uint32_t bb[4][2];
            #pragma unroll
            for (int ni = 0; ni < 4; ni++) {
                int nb = nW + ni * 8 + g;
                bb[ni][0] = Bs[kk + tc    ][nb];
                bb[ni][1] = Bs[kk + tc + 4][nb];
            }
            #pragma unroll
            for (int mi = 0; mi < 4; mi++)
                #pragma unroll
                for (int ni = 0; ni < 4; ni++) {
                    asm volatile(
                        "mma.sync.aligned.m16n8k8.row.col.f32.tf32.tf32.f32 "
                        "{%0,%1,%2,%3}, {%4,%5,%6,%7}, {%8,%9}, {%0,%1,%2,%3};"
                        : "+f"(c[mi][ni][0]), "+f"(c[mi][ni][1]),
                          "+f"(c[mi][ni][2]), "+f"(c[mi][ni][3])
                        : "r"(a[mi][0]), "r"(a[mi][1]), "r"(a[mi][2]), "r"(a[mi][3]),
                          "r"(bb[ni][0]), "r"(bb[ni][1]));
                }
        }
        __syncthreads();
    }

    // ---- epilogue ----
    // element (mi, ni, q): o = oBase+oW+mi*16+g+(q>=2)*8 ; n = nBase+nW+ni*8+tc*2+(q&1)

    if (MODE == 1) {
        const float* Tb = g_T   + (size_t)b * OUT1 * MPTS;
        const int*   ib = g_idx + (size_t)b * NPTS * 3;
        const float* wb = g_wgt + (size_t)b * NPTS * 3;
        #pragma unroll
        for (int ni = 0; ni < 4; ni++) {
            #pragma unroll
            for (int t = 0; t < 2; t++) {
                int n  = nBase + nW + ni * 8 + tc * 2 + t;
                int j0 = ib[n * 3 + 0], j1 = ib[n * 3 + 1], j2 = ib[n * 3 + 2];
                float w0 = wb[n * 3 + 0], w1 = wb[n * 3 + 1], w2 = wb[n * 3 + 2];
                #pragma unroll
                for (int mi = 0; mi < 4; mi++) {
                    #pragma unroll
                    for (int h = 0; h < 2; h++) {
                        int o = oBase + oW + mi * 16 + g + h * 8;
                        const float* tr = Tb + (size_t)o * MPTS;
                        c[mi][ni][h * 2 + t] += w0 * tr[j0] + w1 * tr[j1] + w2 * tr[j2];
                    }
                }
            }
        }
    }

    #pragma unroll
    for (int mi = 0; mi < 4; mi++) {
        #pragma unroll
        for (int h = 0; h < 2; h++) {
            int o = oBase + oW + mi * 16 + g + h * 8;
            float bv = (MODE == 0) ? 0.0f : bias[o];
            float* orow = Cb + (size_t)o * LDC;
            #pragma unroll
            for (int ni = 0; ni < 4; ni++) {
                int n = nBase + nW + ni * 8 + tc * 2;
                float v0 = c[mi][ni][h * 2 + 0] + bv;
                float v1 = c[mi][ni][h * 2 + 1] + bv;
                if (MODE != 0) { v0 = fmaxf(v0, 0.0f); v1 = fmaxf(v1, 0.0f); }
                *reinterpret_cast<float2*>(&orow[n]) = make_float2(v0, v1);
            }
        }
    }
}

// ===========================================================================
extern "C" void kernel_launch(void* const* d_in, const int* in_sizes, int n_in,
                              void* d_out, int out_size)
{
    const float* xyz1    = (const float*)d_in[0];
    const float* xyz2    = (const float*)d_in[1];
    const float* points1 = (const float*)d_in[2];
    const float* points2 = (const float*)d_in[3];
    const float* W1      = (const float*)d_in[4];
    const float* b1      = (const float*)d_in[5];
    const float* W2      = (const float*)d_in[6];
    const float* b2      = (const float*)d_in[7];
    float*       out     = (float*)d_out;

    three_nn_kernel<<<dim3(NPTS / 256, NB), 256>>>(xyz1, xyz2);

    // T = W1[:, :256] @ points2
    gemm_mma<0><<<dim3(MPTS / 128, OUT1 / 128, NB), 256>>>(W1, points2, nullptr, nullptr);

    // y1 = relu(W1[:, 256:] @ points1 + b1 + gathered T)
    gemm_mma<1><<<dim3(NPTS / 128, OUT1 / 128, NB), 256>>>(W1, points1, b1, nullptr);

    // out = relu(W2 @ y1 + b2)
    gemm_mma<2><<<dim3(NPTS / 128, OUT2 / 128, NB), 256>>>(W2, nullptr, b2, out);
}

// round 4
// speedup vs baseline: 2.2490x; 1.6641x over previous
#include <cuda_runtime.h>
#include <math.h>
#include <cstdint>

// Problem constants
#define NB    16
#define NPTS  4096
#define MPTS  1024
#define CH2   256
#define CH1   128
#define OUT1  256
#define OUT2  256
#define LDA_W1 384

// ---- scratch ----
__device__ int   g_idx[NB * NPTS * 3];
__device__ float g_wgt[NB * NPTS * 3];
__device__ float g_Tt [NB * MPTS * OUT1];   // T transposed: [b][m][o], o contiguous
__device__ float g_y1 [NB * OUT1 * NPTS];   // layer-1 activations [b][k][n]

// ===========================================================================
// Kernel 1: three_nn + weights
// ===========================================================================
__global__ __launch_bounds__(256)
void three_nn_kernel(const float* __restrict__ xyz1, const float* __restrict__ xyz2)
{
    __shared__ float sx[MPTS], sy[MPTS], sz[MPTS], ss[MPTS];
    const int b = blockIdx.y;
    const float* x2 = xyz2 + (size_t)b * 3 * MPTS;
    for (int i = threadIdx.x; i < MPTS; i += blockDim.x) {
        float xv = x2[i], yv = x2[MPTS + i], zv = x2[2 * MPTS + i];
        sx[i] = xv; sy[i] = yv; sz[i] = zv;
        ss[i] = xv * xv + yv * yv + zv * zv;
    }
    __syncthreads();

    const int n = blockIdx.x * blockDim.x + threadIdx.x;
    const float* x1 = xyz1 + (size_t)b * 3 * NPTS;
    const float px = x1[n], py = x1[NPTS + n], pz = x1[2 * NPTS + n];
    const float sq1 = px * px + py * py + pz * pz;

    float d0 = 1e30f, d1 = 1e30f, d2 = 1e30f;
    int   i0 = 0, i1 = 0, i2 = 0;

    #pragma unroll 4
    for (int m = 0; m < MPTS; m++) {
        float inner = fmaf(px, sx[m], fmaf(py, sy[m], pz * sz[m]));
        float d = fmaf(-2.0f, inner, sq1 + ss[m]);
        if (d < d2) {
            if (d < d1) {
                d2 = d1; i2 = i1;
                if (d < d0) { d1 = d0; i1 = i0; d0 = d; i0 = m; }
                else        { d1 = d;  i1 = m; }
            } else { d2 = d; i2 = m; }
        }
    }

    float r0 = 1.0f / fmaxf(sqrtf(fmaxf(d0, 1e-20f)), 1e-10f);
    float r1 = 1.0f / fmaxf(sqrtf(fmaxf(d1, 1e-20f)), 1e-10f);
    float r2 = 1.0f / fmaxf(sqrtf(fmaxf(d2, 1e-20f)), 1e-10f);
    float inv = 1.0f / (r0 + r1 + r2);

    const int base = (b * NPTS + n) * 3;
    g_idx[base + 0] = i0; g_idx[base + 1] = i1; g_idx[base + 2] = i2;
    g_wgt[base + 0] = r0 * inv; g_wgt[base + 1] = r1 * inv; g_wgt[base + 2] = r2 * inv;
}

// ===========================================================================
// tf32 mma.sync GEMM, double-buffered smem pipeline, BK=16.
//   MODE 0: Tt  = (W1[:, :256] @ points2)^T                 -> g_Tt [m][o]
//   MODE 1: y1  = relu(W1[:,256:] @ points1 + b1 + gather)  -> g_y1
//   MODE 2: out = relu(W2 @ y1 + b2)                        -> d_out
// CTA tile 128x128, 8 warps (2x4), warp tile 64x32, mma.m16n8k8.tf32.
// ===========================================================================
__device__ __forceinline__ uint32_t f2tf32(float x) {
    uint32_t r;
    asm("cvt.rna.tf32.f32 %0, %1;" : "=r"(r) : "f"(x));
    return r;
}

#define BK     16
#define ASTR   20    // (16+4): frag bank = (20g+tc)%32 = 4g+tc bijective
#define BSTR   136   // (128+8): frag bank = (136k+n)%32 = 8k+n bijective

template <int MODE>
__global__ __launch_bounds__(256)
void gemm_mma(const float* __restrict__ A,
              const float* __restrict__ X,
              const float* __restrict__ bias,
              float*       __restrict__ Cext)
{
    constexpr int K    = (MODE == 1) ? 128 : 256;
    constexpr int NC   = K / BK;
    constexpr int LDA  = (MODE == 2) ? 256 : LDA_W1;
    constexpr int COFF = (MODE == 1) ? 256 : 0;
    constexpr int LDX  = (MODE == 0) ? MPTS : NPTS;
    constexpr int XBS  = (MODE == 0) ? CH2 * MPTS : (MODE == 1) ? CH1 * NPTS : OUT1 * NPTS;

    __shared__ uint32_t As[2][128][ASTR];   // 20.5 KB
    __shared__ uint32_t Bs[2][BK][BSTR];    // 17.4 KB

    const int b     = blockIdx.z;
    const int nBase = blockIdx.x * 128;
    const int oBase = blockIdx.y * 128;
    const int tid   = threadIdx.x;
    const int wid   = tid >> 5;
    const int lane  = tid & 31;
    const int g     = lane >> 2;   // 0..7
    const int tc    = lane & 3;    // 0..3

    const int oW = (wid >> 2) * 64;
    const int nW = (wid & 3) * 32;

    const float* Xb = (MODE == 2) ? (g_y1 + (size_t)b * XBS) : (X + (size_t)b * XBS);

    // gmem load indices (per thread: 2 float4 of A, 2 float4 of B per chunk)
    const int arow0 = tid >> 2;              // 0..63
    const int ac4   = (tid & 3) * 4;         // 0..12
    const int bkr0  = tid >> 5;              // 0..7
    const int bc4   = (tid & 31) * 4;        // 0..124

    float4 pa[2], pb[2];

    auto load_chunk = [&](int c) {
        const int k0 = c * BK;
        pa[0] = *reinterpret_cast<const float4*>(
            &A[(size_t)(oBase + arow0) * LDA + COFF + k0 + ac4]);
        pa[1] = *reinterpret_cast<const float4*>(
            &A[(size_t)(oBase + arow0 + 64) * LDA + COFF + k0 + ac4]);
        pb[0] = *reinterpret_cast<const float4*>(
            &Xb[(size_t)(k0 + bkr0) * LDX + nBase + bc4]);
        pb[1] = *reinterpret_cast<const float4*>(
            &Xb[(size_t)(k0 + bkr0 + 8) * LDX + nBase + bc4]);
    };
    auto store_chunk = [&](int buf) {
        uint4 t0 = make_uint4(f2tf32(pa[0].x), f2tf32(pa[0].y), f2tf32(pa[0].z), f2tf32(pa[0].w));
        uint4 t1 = make_uint4(f2tf32(pa[1].x), f2tf32(pa[1].y), f2tf32(pa[1].z), f2tf32(pa[1].w));
        *reinterpret_cast<uint4*>(&As[buf][arow0     ][ac4]) = t0;
        *reinterpret_cast<uint4*>(&As[buf][arow0 + 64][ac4]) = t1;
        uint4 u0 = make_uint4(f2tf32(pb[0].x), f2tf32(pb[0].y), f2tf32(pb[0].z), f2tf32(pb[0].w));
        uint4 u1 = make_uint4(f2tf32(pb[1].x), f2tf32(pb[1].y), f2tf32(pb[1].z), f2tf32(pb[1].w));
        *reinterpret_cast<uint4*>(&Bs[buf][bkr0    ][bc4]) = u0;
        *reinterpret_cast<uint4*>(&Bs[buf][bkr0 + 8][bc4]) = u1;
    };

    float c[4][4][4];
    #pragma unroll
    for (int mi = 0; mi < 4; mi++)
        #pragma unroll
        for (int ni = 0; ni < 4; ni++)
            #pragma unroll
            for (int q = 0; q < 4; q++) c[mi][ni][q] = 0.0f;

    load_chunk(0);
    store_chunk(0);
    __syncthreads();

    for (int cc = 0; cc < NC; cc++) {
        const int cur = cc & 1;
        if (cc + 1 < NC) load_chunk(cc + 1);

        #pragma unroll
        for (int kk = 0; kk < BK; kk += 8) {
            uint32_t a[4][4];
            #pragma unroll
            for (int mi = 0; mi < 4; mi++) {
                int rb = oW + mi * 16;
                a[mi][0] = As[cur][rb + g    ][kk + tc    ];
                a[mi][1] = As[cur][rb + g + 8][kk + tc    ];
                a[mi][2] = As[cur][rb + g    ][kk + tc + 4];
                a[mi][3] = As[cur][rb + g + 8][kk + tc + 4];
            }
            uint32_t bb[4][2];
            #pragma unroll
            for (int ni = 0; ni < 4; ni++) {
                int nb = nW + ni * 8 + g;
                bb[ni][0] = Bs[cur][kk + tc    ][nb];
                bb[ni][1] = Bs[cur][kk + tc + 4][nb];
            }
            #pragma unroll
            for (int mi = 0; mi < 4; mi++)
                #pragma unroll
                for (int ni = 0; ni < 4; ni++) {
                    asm volatile(
                        "mma.sync.aligned.m16n8k8.row.col.f32.tf32.tf32.f32 "
                        "{%0,%1,%2,%3}, {%4,%5,%6,%7}, {%8,%9}, {%0,%1,%2,%3};"
                        : "+f"(c[mi][ni][0]), "+f"(c[mi][ni][1]),
                          "+f"(c[mi][ni][2]), "+f"(c[mi][ni][3])
                        : "r"(a[mi][0]), "r"(a[mi][1]), "r"(a[mi][2]), "r"(a[mi][3]),
                          "r"(bb[ni][0]), "r"(bb[ni][1]));
                }
        }

        if (cc + 1 < NC) {
            store_chunk((cc + 1) & 1);
            __syncthreads();
        }
    }

    // ---- epilogue ----
    // element (mi, ni, q): o = oBase+oW+mi*16+g+(q>=2)*8 ; n = nBase+nW+ni*8+tc*2+(q&1)

    if (MODE == 0) {
        // store transposed: Tt[m][o], o contiguous
        float* Cb = g_Tt + (size_t)b * MPTS * OUT1;
        #pragma unroll
        for (int ni = 0; ni < 4; ni++) {
            #pragma unroll
            for (int t = 0; t < 2; t++) {
                int m = nBase + nW + ni * 8 + tc * 2 + t;
                float* mrow = Cb + (size_t)m * OUT1;
                #pragma unroll
                for (int mi = 0; mi < 4; mi++) {
                    #pragma unroll
                    for (int h = 0; h < 2; h++) {
                        int o = oBase + oW + mi * 16 + g + h * 8;
                        mrow[o] = c[mi][ni][h * 2 + t];
                    }
                }
            }
        }
        return;
    }

    constexpr int LDC = NPTS;
    float* Cb = (MODE == 1) ? (g_y1 + (size_t)b * OUT1 * NPTS)
                            : (Cext + (size_t)b * OUT1 * NPTS);

    if (MODE == 1) {
        // gather from transposed T: rows are contiguous in o
        const float* Tb = g_Tt + (size_t)b * MPTS * OUT1;
        const int*   ib = g_idx + (size_t)b * NPTS * 3;
        const float* wb = g_wgt + (size_t)b * NPTS * 3;
        #pragma unroll
        for (int ni = 0; ni < 4; ni++) {
            #pragma unroll
            for (int t = 0; t < 2; t++) {
                int n  = nBase + nW + ni * 8 + tc * 2 + t;
                int j0 = ib[n * 3 + 0], j1 = ib[n * 3 + 1], j2 = ib[n * 3 + 2];
                float w0 = wb[n * 3 + 0], w1 = wb[n * 3 + 1], w2 = wb[n * 3 + 2];
                const float* r0 = Tb + (size_t)j0 * OUT1;
                const float* r1 = Tb + (size_t)j1 * OUT1;
                const float* r2 = Tb + (size_t)j2 * OUT1;
                #pragma unroll
                for (int mi = 0; mi < 4; mi++) {
                    #pragma unroll
                    for (int h = 0; h < 2; h++) {
                        int o = oBase + oW + mi * 16 + g + h * 8;
                        c[mi][ni][h * 2 + t] +=
                            w0 * __ldg(&r0[o]) + w1 * __ldg(&r1[o]) + w2 * __ldg(&r2[o]);
                    }
                }
            }
        }
    }

    #pragma unroll
    for (int mi = 0; mi < 4; mi++) {
        #pragma unroll
        for (int h = 0; h < 2; h++) {
            int o = oBase + oW + mi * 16 + g + h * 8;
            float bv = bias[o];
            float* orow = Cb + (size_t)o * LDC;
            #pragma unroll
            for (int ni = 0; ni < 4; ni++) {
                int n = nBase + nW + ni * 8 + tc * 2;
                float v0 = fmaxf(c[mi][ni][h * 2 + 0] + bv, 0.0f);
                float v1 = fmaxf(c[mi][ni][h * 2 + 1] + bv, 0.0f);
                *reinterpret_cast<float2*>(&orow[n]) = make_float2(v0, v1);
            }
        }
    }
}

// ===========================================================================
extern "C" void kernel_launch(void* const* d_in, const int* in_sizes, int n_in,
                              void* d_out, int out_size)
{
    const float* xyz1    = (const float*)d_in[0];
    const float* xyz2    = (const float*)d_in[1];
    const float* points1 = (const float*)d_in[2];
    const float* points2 = (const float*)d_in[3];
    const float* W1      = (const float*)d_in[4];
    const float* b1      = (const float*)d_in[5];
    const float* W2      = (const float*)d_in[6];
    const float* b2      = (const float*)d_in[7];
    float*       out     = (float*)d_out;

    three_nn_kernel<<<dim3(NPTS / 256, NB), 256>>>(xyz1, xyz2);

    // Tt = (W1[:, :256] @ points2)^T
    gemm_mma<0><<<dim3(MPTS / 128, OUT1 / 128, NB), 256>>>(W1, points2, nullptr, nullptr);

    // y1 = relu(W1[:, 256:] @ points1 + b1 + gathered Tt)
    gemm_mma<1><<<dim3(NPTS / 128, OUT1 / 128, NB), 256>>>(W1, points1, b1, nullptr);

    // out = relu(W2 @ y1 + b2)
    gemm_mma<2><<<dim3(NPTS / 128, OUT2 / 128, NB), 256>>>(W2, nullptr, b2, out);
}